// round 8
// baseline (speedup 1.0000x reference)
#include <cuda_runtime.h>
#include <cuda_bf16.h>

// Problem constants
#define BB     16
#define ORDER  2
#define NC     2      // convs per order
#define IC     (ORDER*NC)   // 4 modules per (b)
#define NN     512
#define DD     128
#define HH     8
#define DHH    16

#define DTILE  128
#define STILE  64
#define L2E    1.4426950408889634f

// Scratch (device globals; no allocation allowed)
__device__ float g_xp  [IC*BB*NN*DD];   // projected features per module
__device__ float g_gat [IC*BB*NN*DD];   // per-conv GAT outputs

__device__ __forceinline__ unsigned long long ffma2(unsigned long long a,
                                                    unsigned long long b,
                                                    unsigned long long c) {
    unsigned long long d;
    asm("fma.rn.f32x2 %0, %1, %2, %3;" : "=l"(d) : "l"(a), "l"(b), "l"(c));
    return d;
}

// ---------------------------------------------------------------------------
// Kernel 1: projection GEMM.  xp[ic,b,n,:] = x[b,i,n,:] @ W[ic]^T + pb[ic]
// Block: 64 rows x 128 cols, K=128.  grid (128, IC), 256 threads.
// ---------------------------------------------------------------------------
__global__ void __launch_bounds__(256, 2)
k_project(const float* __restrict__ x, const float* __restrict__ W,
          const float* __restrict__ pb) {
    extern __shared__ float sm[];
    float* xs = sm;             // [64][128]
    float* ws = sm + 64*128;    // [128][129]  (padded)

    const int ic = blockIdx.y;
    const int i  = ic >> 1;
    const int m0 = blockIdx.x * 64;
    const int b  = m0 / NN;
    const int n0 = m0 % NN;
    const int tid = threadIdx.x;

    const float* xbase = x + ((size_t)(b*ORDER + i)*NN + n0)*DD;
    const float* wbase = W + (size_t)ic*DD*DD;

    // load x tile (float4) and W tile (scalar, padded stride 129)
    for (int idx = tid; idx < 64*32; idx += 256) {
        int s = idx >> 5, q = idx & 31;
        *(float4*)(xs + s*128 + q*4) = *(const float4*)(xbase + s*DD + q*4);
    }
    for (int idx = tid; idx < 128*128; idx += 256) {
        int r = idx >> 7, k = idx & 127;
        ws[r*129 + k] = wbase[idx];
    }
    __syncthreads();

    const int tx = tid & 31;   // col base (cols tx + cc*32)
    const int ty = tid >> 5;   // row group (rows ty*8 + r)

    float acc[8][4];
#pragma unroll
    for (int r = 0; r < 8; r++)
#pragma unroll
        for (int cc = 0; cc < 4; cc++) acc[r][cc] = 0.f;

#pragma unroll 4
    for (int k = 0; k < 128; k++) {
        float wr[4], xr[8];
#pragma unroll
        for (int cc = 0; cc < 4; cc++) wr[cc] = ws[(tx + cc*32)*129 + k];
#pragma unroll
        for (int r = 0; r < 8; r++)   xr[r]  = xs[(ty*8 + r)*128 + k];
#pragma unroll
        for (int r = 0; r < 8; r++)
#pragma unroll
            for (int cc = 0; cc < 4; cc++)
                acc[r][cc] = fmaf(xr[r], wr[cc], acc[r][cc]);
    }

    float pbv[4];
#pragma unroll
    for (int cc = 0; cc < 4; cc++) pbv[cc] = pb[ic*DD + tx + cc*32];

    float* obase = g_xp + ((size_t)(ic*BB + b)*NN + n0)*DD;
#pragma unroll
    for (int r = 0; r < 8; r++) {
        float* orow = obase + (ty*8 + r)*DD;
#pragma unroll
        for (int cc = 0; cc < 4; cc++)
            orow[tx + cc*32] = acc[r][cc] + pbv[cc];
    }
}

// ---------------------------------------------------------------------------
// Kernel 2: fused attention (scores computed in-kernel).
// For module (ic,b), dst tile of 128:
//   ssrc[s,h]  = <xh[s,h,:], att_src[ic,h,:]>   (from staged smem tile)
//   sdst[d,h]  = <xh[d,h,:], att_dst[ic,h,:]>   (prologue, from g_xp/L2)
//   e[s,d,h]   = exp2( m[s,d] * log2e * leaky(ssrc+sdst) )   (m in {0,1})
//   gat[d,h*16+f] = (sum_s e*xh[s,h,f]) / (sum_s e) + xp[d,h*16+f] + bias
// Thread: h = tid&7, dq = tid>>3; owns 4 dst x 1 head x 16 feats (f32x2 accum).
// ---------------------------------------------------------------------------
__global__ void __launch_bounds__(256, 2)
k_attn(const int* __restrict__ A, const float* __restrict__ att_src,
       const float* __restrict__ att_dst, const float* __restrict__ bias) {
    extern __shared__ float sm[];
    float* sh_xh   = sm;                       // [STILE][160]  (head stride 20)
    float* sh_ssrc = sm + STILE*160;           // [STILE][8]
    float* sh_m    = sm + STILE*160 + STILE*8; // [STILE][128]  (0 or log2e)
    float* sh_as   = sm + STILE*160 + STILE*8 + STILE*DTILE;  // [128] att_src[ic]

    const int icb = blockIdx.y;               // ic*B + b
    const int ic  = icb >> 4;
    const int b   = icb & 15;
    const int i   = ic >> 1;
    const int c   = ic & 1;
    const int d0  = blockIdx.x * DTILE;
    const int tid = threadIdx.x;
    const int h   = tid & 7;
    const int dq  = tid >> 3;                 // 0..31

    const size_t mb = (size_t)icb * NN * DD;  // module base in g_xp / g_gat
    const int*  Ab  = A + ((size_t)(b*ORDER + i)*NN)*NN;

    // stage att_src[ic] (128 floats); consumed after the first in-loop barrier
    if (tid < DD) sh_as[tid] = att_src[ic*DD + tid];

    // prologue: sdst for this thread's 4 dsts (g_xp is L2-hot after k_project)
    float adv[16];
    {
        const float4* ap = (const float4*)(att_dst + ic*DD + h*DHH);
#pragma unroll
        for (int q = 0; q < 4; q++) {
            float4 v = ap[q];
            adv[q*4+0] = v.x; adv[q*4+1] = v.y; adv[q*4+2] = v.z; adv[q*4+3] = v.w;
        }
    }
    float sdst[4];
#pragma unroll
    for (int j = 0; j < 4; j++) {
        const float4* xp4 = (const float4*)(g_xp + mb + (size_t)(d0 + dq*4 + j)*DD + h*DHH);
        float sd = 0.f;
#pragma unroll
        for (int q = 0; q < 4; q++) {
            float4 v = xp4[q];
            sd += v.x*adv[q*4+0] + v.y*adv[q*4+1] + v.z*adv[q*4+2] + v.w*adv[q*4+3];
        }
        sdst[j] = sd;
    }

    unsigned long long acc[4][8];
    float zz[4];
#pragma unroll
    for (int j = 0; j < 4; j++) {
        zz[j] = 0.f;
#pragma unroll
        for (int q = 0; q < 8; q++) acc[j][q] = 0ull;
    }

    for (int s0 = 0; s0 < NN; s0 += STILE) {
        __syncthreads();
        // xh tile, padded per-head layout
        for (int idx = tid; idx < STILE*32; idx += 256) {
            int s = idx >> 5, q = idx & 31;
            int h2 = q >> 2, fq = q & 3;
            float4 v = *(const float4*)(g_xp + mb + (size_t)(s0 + s)*DD + q*4);
            *(float4*)(sh_xh + s*160 + h2*20 + fq*4) = v;
        }
        // mask, pre-multiplied by log2e
        for (int idx = tid; idx < STILE*DTILE; idx += 256) {
            int s = idx >> 7, dl = idx & 127;
            int a = Ab[(size_t)(s0 + s)*NN + d0 + dl];
            bool in = c ? (a == 3 || a == 4) : (a == 2 || a == 4);
            sh_m[idx] = in ? L2E : 0.f;
        }
        __syncthreads();
        // src scores from the staged tile: 512 dots, 2 per thread (fixed h per thread)
        for (int idx = tid; idx < STILE*HH; idx += 256) {
            int s2 = idx >> 3, h2 = idx & 7;
            const float* xr = sh_xh + s2*160 + h2*20;
            const float* ar = sh_as + h2*DHH;
            float sc = 0.f;
#pragma unroll
            for (int f = 0; f < 16; f++) sc = fmaf(xr[f], ar[f], sc);
            sh_ssrc[idx] = sc;
        }
        __syncthreads();

        for (int s = 0; s < STILE; s++) {
            const float* xrow = sh_xh + s*160 + h*20;
            ulonglong2 u0 = *(const ulonglong2*)(xrow);
            ulonglong2 u1 = *(const ulonglong2*)(xrow + 4);
            ulonglong2 u2 = *(const ulonglong2*)(xrow + 8);
            ulonglong2 u3 = *(const ulonglong2*)(xrow + 12);
            float ss = sh_ssrc[s*8 + h];
            float4 mv = *(const float4*)(sh_m + s*128 + dq*4);
#pragma unroll
            for (int j = 0; j < 4; j++) {
                float m = (j == 0) ? mv.x : (j == 1) ? mv.y : (j == 2) ? mv.z : mv.w;
                float t = ss + sdst[j];
                t = fmaxf(t, 0.2f*t);          // leaky relu
                float e;
                asm("ex2.approx.ftz.f32 %0, %1;" : "=f"(e) : "f"(t*m));
                zz[j] += e;
                unsigned eu = __float_as_uint(e);
                unsigned long long e2;
                asm("mov.b64 %0, {%1, %1};" : "=l"(e2) : "r"(eu));
                acc[j][0] = ffma2(e2, u0.x, acc[j][0]);
                acc[j][1] = ffma2(e2, u0.y, acc[j][1]);
                acc[j][2] = ffma2(e2, u1.x, acc[j][2]);
                acc[j][3] = ffma2(e2, u1.y, acc[j][3]);
                acc[j][4] = ffma2(e2, u2.x, acc[j][4]);
                acc[j][5] = ffma2(e2, u2.y, acc[j][5]);
                acc[j][6] = ffma2(e2, u3.x, acc[j][6]);
                acc[j][7] = ffma2(e2, u3.y, acc[j][7]);
            }
        }
    }

    // epilogue: normalize, add self-loop xp + bias
    const float4* bq = (const float4*)(bias + ic*DD + h*DHH);
    float4 bv[4];
#pragma unroll
    for (int q = 0; q < 4; q++) bv[q] = bq[q];

#pragma unroll
    for (int j = 0; j < 4; j++) {
        int d = d0 + dq*4 + j;
        float invz = 1.0f / zz[j];
        size_t base = mb + (size_t)d*DD + h*DHH;
        const float4* xq = (const float4*)(g_xp + base);
        float4* oq = (float4*)(g_gat + base);
#pragma unroll
        for (int q = 0; q < 4; q++) {
            unsigned long long lo = acc[j][2*q], hi = acc[j][2*q + 1];
            float a0 = __uint_as_float((unsigned)(lo & 0xffffffffu));
            float a1 = __uint_as_float((unsigned)(lo >> 32));
            float a2 = __uint_as_float((unsigned)(hi & 0xffffffffu));
            float a3 = __uint_as_float((unsigned)(hi >> 32));
            float4 xv = xq[q];
            float4 o;
            o.x = a0*invz + xv.x + bv[q].x;
            o.y = a1*invz + xv.y + bv[q].y;
            o.z = a2*invz + xv.z + bv[q].z;
            o.w = a3*invz + xv.w + bv[q].w;
            oq[q] = o;
        }
    }
}

// ---------------------------------------------------------------------------
// Kernel 3: combine convs + order mean.
//   h_i = gat[i,0]+gat[i,1];  out[:,i] = 1.5*h_i + 0.5*h_{1-i}
// ---------------------------------------------------------------------------
__global__ void k_combine(float* __restrict__ out) {
    int idx = blockIdx.x * blockDim.x + threadIdx.x;  // B*N*D/4 = 262144
    int b = idx >> 14;            // P = N*D/4 = 16384
    int r = idx & 16383;
    const float4* g = (const float4*)g_gat;
    float4 a0 = g[(size_t)(0*BB + b)*16384 + r];
    float4 a1 = g[(size_t)(1*BB + b)*16384 + r];
    float4 a2 = g[(size_t)(2*BB + b)*16384 + r];
    float4 a3 = g[(size_t)(3*BB + b)*16384 + r];
    float4 h0, h1, o0, o1;
    h0.x = a0.x + a1.x; h0.y = a0.y + a1.y; h0.z = a0.z + a1.z; h0.w = a0.w + a1.w;
    h1.x = a2.x + a3.x; h1.y = a2.y + a3.y; h1.z = a2.z + a3.z; h1.w = a2.w + a3.w;
    o0.x = 1.5f*h0.x + 0.5f*h1.x; o0.y = 1.5f*h0.y + 0.5f*h1.y;
    o0.z = 1.5f*h0.z + 0.5f*h1.z; o0.w = 1.5f*h0.w + 0.5f*h1.w;
    o1.x = 1.5f*h1.x + 0.5f*h0.x; o1.y = 1.5f*h1.y + 0.5f*h0.y;
    o1.z = 1.5f*h1.z + 0.5f*h0.z; o1.w = 1.5f*h1.w + 0.5f*h0.w;
    float4* o = (float4*)out;
    o[(size_t)(b*2 + 0)*16384 + r] = o0;
    o[(size_t)(b*2 + 1)*16384 + r] = o1;
}

// ---------------------------------------------------------------------------
extern "C" void kernel_launch(void* const* d_in, const int* in_sizes, int n_in,
                              void* d_out, int out_size) {
    (void)in_sizes; (void)n_in; (void)out_size;
    const float* x    = (const float*)d_in[0];
    const int*   A    = (const int*)  d_in[1];
    const float* W    = (const float*)d_in[2];
    const float* pb   = (const float*)d_in[3];
    const float* asrc = (const float*)d_in[4];
    const float* adst = (const float*)d_in[5];
    const float* bias = (const float*)d_in[6];
    float* out = (float*)d_out;

    const int SMEM_PROJ = (64*128 + 128*129) * 4;                     // 98816 B
    const int SMEM_ATTN = (STILE*160 + STILE*8 + STILE*DTILE + DD) * 4;  // 76288 B
    cudaFuncSetAttribute(k_project, cudaFuncAttributeMaxDynamicSharedMemorySize, SMEM_PROJ);
    cudaFuncSetAttribute(k_attn,    cudaFuncAttributeMaxDynamicSharedMemorySize, SMEM_ATTN);

    k_project<<<dim3(128, IC), 256, SMEM_PROJ>>>(x, W, pb);
    k_attn   <<<dim3(NN/DTILE, IC*BB), 256, SMEM_ATTN>>>(A, asrc, adst, bias);
    k_combine<<<1024, 256>>>(out);
}